// round 2
// baseline (speedup 1.0000x reference)
#include <cuda_runtime.h>
#include <cuda_bf16.h>

// Problem shapes (fixed by the dataset)
#define B_   16
#define S_   1024
#define VD_  1024
#define TD_  768
#define H_   512
#define EPS_ 1e-8f

// GEMM tiling
#define BM 128
#define BN 128
#define BK 8
#define TM 8
#define TN 8
#define NTHREADS 256

// Scratch (allocation-free rule: device globals)
__device__ float g_v [B_ * S_ * H_];   // 32 MB
__device__ float g_t [B_ * S_ * H_];   // 32 MB
__device__ float g_vn[B_ * S_];
__device__ float g_tn[B_ * S_];

// ---------------------------------------------------------------------------
// Projection GEMM (NT): C[m,n] = sum_k A[m,k] * W[n,k] + bias[n]
// A: [M, K] row-major, W: [N=512, K] row-major, C: [M, 512]
// Grid: (N/BN, M/BM). All dims divide tile sizes exactly (no guards needed).
// ---------------------------------------------------------------------------
__global__ void __launch_bounds__(NTHREADS, 2)
proj_kernel(const float* __restrict__ A, const float* __restrict__ W,
            const float* __restrict__ bias, float* __restrict__ C, int K)
{
    __shared__ float As[BK][BM];
    __shared__ float Ws[BK][BN];

    const int t  = threadIdx.x;
    const long m0 = (long)blockIdx.y * BM;
    const int  n0 = blockIdx.x * BN;

    // global->smem load mapping: 128 rows x 8 cols per tile = 256 float4
    const int lr = t >> 1;          // 0..127
    const int lc = (t & 1) * 4;     // 0 or 4

    // compute mapping: 16x16 thread grid, 8x8 per thread
    const int tx = t & 15;
    const int ty = t >> 4;

    const float* Ap = A + (m0 + lr) * (long)K + lc;
    const float* Wp = W + (long)(n0 + lr) * K + lc;

    float acc[TM][TN];
    #pragma unroll
    for (int i = 0; i < TM; i++)
        #pragma unroll
        for (int j = 0; j < TN; j++) acc[i][j] = 0.f;

    for (int k0 = 0; k0 < K; k0 += BK) {
        float4 av = *(const float4*)(Ap + k0);
        float4 wv = *(const float4*)(Wp + k0);
        As[lc + 0][lr] = av.x; As[lc + 1][lr] = av.y;
        As[lc + 2][lr] = av.z; As[lc + 3][lr] = av.w;
        Ws[lc + 0][lr] = wv.x; Ws[lc + 1][lr] = wv.y;
        Ws[lc + 2][lr] = wv.z; Ws[lc + 3][lr] = wv.w;
        __syncthreads();

        #pragma unroll
        for (int k = 0; k < BK; k++) {
            float a[TM], b[TN];
            #pragma unroll
            for (int i = 0; i < TM; i++) a[i] = As[k][ty * TM + i];
            #pragma unroll
            for (int j = 0; j < TN; j++) b[j] = Ws[k][tx * TN + j];
            #pragma unroll
            for (int i = 0; i < TM; i++)
                #pragma unroll
                for (int j = 0; j < TN; j++)
                    acc[i][j] = fmaf(a[i], b[j], acc[i][j]);
        }
        __syncthreads();
    }

    // epilogue: +bias, store
    #pragma unroll
    for (int i = 0; i < TM; i++) {
        const long row = m0 + ty * TM + i;
        #pragma unroll
        for (int j = 0; j < TN; j++) {
            const int col = n0 + tx * TN + j;
            C[row * H_ + col] = acc[i][j] + bias[col];
        }
    }
}

// ---------------------------------------------------------------------------
// Row L2 norms over H=512: one warp per row, float4 loads, warp reduce.
// ---------------------------------------------------------------------------
__global__ void rownorm_kernel(const float* __restrict__ X, float* __restrict__ out)
{
    const int row  = blockIdx.x * (blockDim.x >> 5) + (threadIdx.x >> 5);
    const int lane = threadIdx.x & 31;
    const float4* p = (const float4*)(X + (long)row * H_);
    float s = 0.f;
    #pragma unroll
    for (int i = lane; i < H_ / 4; i += 32) {
        float4 v = p[i];
        s += v.x * v.x + v.y * v.y + v.z * v.z + v.w * v.w;
    }
    #pragma unroll
    for (int o = 16; o; o >>= 1) s += __shfl_xor_sync(0xFFFFFFFFu, s, o);
    if (lane == 0) out[row] = sqrtf(s);
}

// ---------------------------------------------------------------------------
// Batched similarity GEMM (NT) with fused cosine epilogue:
// C[b,i,j] = dot(v[b,i,:], t[b,j,:]) / max(vn[b,i]*tn[b,j], EPS)
// Per batch: M=N=1024, K=512. Grid: (8, 8, 16).
// ---------------------------------------------------------------------------
__global__ void __launch_bounds__(NTHREADS, 2)
sim_kernel(const float* __restrict__ V, const float* __restrict__ T,
           const float* __restrict__ VN, const float* __restrict__ TNRM,
           float* __restrict__ C)
{
    __shared__ float As[BK][BM];
    __shared__ float Bs[BK][BN];

    const int bz = blockIdx.z;
    const float* A  = V + (long)bz * S_ * H_;
    const float* Bm = T + (long)bz * S_ * H_;
    float*       Cb = C + (long)bz * S_ * S_;
    const float* vn = VN   + bz * S_;
    const float* tn = TNRM + bz * S_;

    const int t  = threadIdx.x;
    const int m0 = blockIdx.y * BM;
    const int n0 = blockIdx.x * BN;

    const int lr = t >> 1;
    const int lc = (t & 1) * 4;
    const int tx = t & 15;
    const int ty = t >> 4;

    const float* Ap = A  + (long)(m0 + lr) * H_ + lc;
    const float* Bp = Bm + (long)(n0 + lr) * H_ + lc;

    float acc[TM][TN];
    #pragma unroll
    for (int i = 0; i < TM; i++)
        #pragma unroll
        for (int j = 0; j < TN; j++) acc[i][j] = 0.f;

    for (int k0 = 0; k0 < H_; k0 += BK) {
        float4 av = *(const float4*)(Ap + k0);
        float4 bv = *(const float4*)(Bp + k0);
        As[lc + 0][lr] = av.x; As[lc + 1][lr] = av.y;
        As[lc + 2][lr] = av.z; As[lc + 3][lr] = av.w;
        Bs[lc + 0][lr] = bv.x; Bs[lc + 1][lr] = bv.y;
        Bs[lc + 2][lr] = bv.z; Bs[lc + 3][lr] = bv.w;
        __syncthreads();

        #pragma unroll
        for (int k = 0; k < BK; k++) {
            float a[TM], b[TN];
            #pragma unroll
            for (int i = 0; i < TM; i++) a[i] = As[k][ty * TM + i];
            #pragma unroll
            for (int j = 0; j < TN; j++) b[j] = Bs[k][tx * TN + j];
            #pragma unroll
            for (int i = 0; i < TM; i++)
                #pragma unroll
                for (int j = 0; j < TN; j++)
                    acc[i][j] = fmaf(a[i], b[j], acc[i][j]);
        }
        __syncthreads();
    }

    // fused cosine-similarity epilogue
    float nvr[TM], ntc[TN];
    #pragma unroll
    for (int i = 0; i < TM; i++) nvr[i] = vn[m0 + ty * TM + i];
    #pragma unroll
    for (int j = 0; j < TN; j++) ntc[j] = tn[n0 + tx * TN + j];

    #pragma unroll
    for (int i = 0; i < TM; i++) {
        const long row = m0 + ty * TM + i;
        #pragma unroll
        for (int j = 0; j < TN; j++) {
            const int col = n0 + tx * TN + j;
            const float denom = fmaxf(nvr[i] * ntc[j], EPS_);
            Cb[row * S_ + col] = acc[i][j] / denom;
        }
    }
}

// ---------------------------------------------------------------------------
extern "C" void kernel_launch(void* const* d_in, const int* in_sizes, int n_in,
                              void* d_out, int out_size)
{
    const float* visual = (const float*)d_in[0];  // [16,1024,1024]
    const float* text   = (const float*)d_in[1];  // [16,1024,768]
    const float* Wv     = (const float*)d_in[2];  // [512,1024]
    const float* bv     = (const float*)d_in[3];  // [512]
    const float* Wt     = (const float*)d_in[4];  // [512,768]
    const float* bt     = (const float*)d_in[5];  // [512]
    float* out = (float*)d_out;                   // [16,1024,1024]

    float *v, *tt, *vn, *tn;
    cudaGetSymbolAddress((void**)&v,  g_v);
    cudaGetSymbolAddress((void**)&tt, g_t);
    cudaGetSymbolAddress((void**)&vn, g_vn);
    cudaGetSymbolAddress((void**)&tn, g_tn);

    const int M = B_ * S_;  // 16384

    // Projections: M x 512, K = 1024 / 768
    proj_kernel<<<dim3(H_ / BN, M / BM), NTHREADS>>>(visual, Wv, bv, v,  VD_);
    proj_kernel<<<dim3(H_ / BN, M / BM), NTHREADS>>>(text,   Wt, bt, tt, TD_);

    // Row norms: one warp per row, 8 warps per block
    rownorm_kernel<<<M / 8, 256>>>(v,  vn);
    rownorm_kernel<<<M / 8, 256>>>(tt, tn);

    // Batched similarity with fused cosine epilogue
    sim_kernel<<<dim3(S_ / BN, S_ / BM, B_), NTHREADS>>>(v, tt, vn, tn, out);
}

// round 6
// speedup vs baseline: 7.7035x; 7.7035x over previous
#include <cuda_runtime.h>
#include <cuda_bf16.h>
#include <cstdint>

// Problem shapes (fixed by the dataset)
#define B_   16
#define S_   1024
#define VD_  1024
#define TD_  768
#define H_   512
#define EPS_ 1e-8f

// tcgen05 is arch-specific: only compile it in the sm_103a pass. The plain
// compute_103 pass (extra forward-compat embed) gets a SIMT fallback with
// identical launch geometry, so whichever cubin the runtime picks is correct.
#if defined(__CUDA_ARCH_FEAT_SM103_ALL) || \
    (defined(__CUDA_ARCH_SPECIFIC__) && (__CUDA_ARCH_SPECIFIC__ == 1030))
#define HAS_TCGEN05 1
#else
#define HAS_TCGEN05 0
#endif

// ---------------------------------------------------------------------------
// PTX helpers
// ---------------------------------------------------------------------------
__device__ __forceinline__ uint32_t smem_to_u32(const void* p) {
    uint32_t a;
    asm("{ .reg .u64 t; cvta.to.shared.u64 t, %1; cvt.u32.u64 %0, t; }"
        : "=r"(a) : "l"(p));
    return a;
}
__device__ __forceinline__ uint32_t elect_one_pred() {
    uint32_t pred;
    asm volatile("{\n\t.reg .pred p;\n\telect.sync _|p, 0xFFFFFFFF;\n\t"
                 "selp.b32 %0, 1, 0, p;\n\t}" : "=r"(pred));
    return pred;
}
#define SMEM_SWIZZLE_128B(off) ((off) ^ (((off) >> 3) & 0x70))

static constexpr uint64_t SMEM_DESC_BASE_SW128 =
    (uint64_t(2) << 61) | (uint64_t(1) << 46) | (uint64_t(64) << 32) | (uint64_t(1) << 16);
#define MAKE_SMEM_DESC(base_addr) \
    (SMEM_DESC_BASE_SW128 | ((uint64_t)((base_addr) >> 4) & 0x3FFF))

#if HAS_TCGEN05
#define TCGEN05_ALLOC(smem_result_addr, nCols) \
    asm volatile("tcgen05.alloc.cta_group::1.sync.aligned.shared::cta.b32 [%0], %1;" \
        :: "r"((uint32_t)(smem_result_addr)), "r"((uint32_t)(nCols)) : "memory")
#define TCGEN05_DEALLOC(tmem_addr, nCols) \
    asm volatile("tcgen05.dealloc.cta_group::1.sync.aligned.b32 %0, %1;" \
        :: "r"(tmem_addr), "r"((uint32_t)(nCols)))
#define TCGEN05_RELINQUISH_ALLOC_PERMIT() \
    asm volatile("tcgen05.relinquish_alloc_permit.cta_group::1.sync.aligned;")
#define TCGEN05_COMMIT(mbar_smem_addr) \
    asm volatile("tcgen05.commit.cta_group::1.mbarrier::arrive::one.shared::cluster.b64 [%0];" \
        :: "r"((uint32_t)(mbar_smem_addr)) : "memory")
#define TCGEN05_WAIT_LD()  asm volatile("tcgen05.wait::ld.sync.aligned;" ::: "memory")
#define TCGEN05_FENCE_BEFORE() asm volatile("tcgen05.fence::before_thread_sync;" ::: "memory")
#define TCGEN05_FENCE_AFTER()  asm volatile("tcgen05.fence::after_thread_sync;"  ::: "memory")

#define TCGEN05_LD_32X32B_X32(r, tmem_addr) \
    asm volatile("tcgen05.ld.sync.aligned.32x32b.x32.b32 " \
        "{%0, %1, %2, %3, %4, %5, %6, %7, " \
        " %8, %9, %10, %11, %12, %13, %14, %15, " \
        " %16, %17, %18, %19, %20, %21, %22, %23, " \
        " %24, %25, %26, %27, %28, %29, %30, %31}, [%32];" \
        : "=r"((r)[0]),  "=r"((r)[1]),  "=r"((r)[2]),  "=r"((r)[3]), \
          "=r"((r)[4]),  "=r"((r)[5]),  "=r"((r)[6]),  "=r"((r)[7]), \
          "=r"((r)[8]),  "=r"((r)[9]),  "=r"((r)[10]), "=r"((r)[11]), \
          "=r"((r)[12]), "=r"((r)[13]), "=r"((r)[14]), "=r"((r)[15]), \
          "=r"((r)[16]), "=r"((r)[17]), "=r"((r)[18]), "=r"((r)[19]), \
          "=r"((r)[20]), "=r"((r)[21]), "=r"((r)[22]), "=r"((r)[23]), \
          "=r"((r)[24]), "=r"((r)[25]), "=r"((r)[26]), "=r"((r)[27]), \
          "=r"((r)[28]), "=r"((r)[29]), "=r"((r)[30]), "=r"((r)[31]) \
        : "r"(tmem_addr))

// tf32 MMA: D[128,256] += A(smem desc) * B(smem desc)^T, K=8 per dispatch
#define TCGEN05_MMA_TF32(d_tmem, a_desc, b_desc, idesc, enable_d) do { \
    uint32_t _en = (enable_d) ? 1u : 0u; uint32_t _z = 0u; \
    asm volatile("{\n\t.reg .pred p;\n\tsetp.ne.u32 p, %5, 0;\n\t" \
        "tcgen05.mma.cta_group::1.kind::tf32 [%0], %1, %2, %3, {%4, %4, %4, %4}, p;\n\t}" \
        :: "r"(d_tmem), "l"(a_desc), "l"(b_desc), "r"(idesc), "r"(_z), "r"(_en) \
        : "memory"); \
} while(0)
#endif  // HAS_TCGEN05

#define FENCE_PROXY_ASYNC_SHARED_CTA() \
    asm volatile("fence.proxy.async.shared::cta;" ::: "memory")
#define MBARRIER_INIT(mbar, count) \
    asm volatile("mbarrier.init.shared.b64 [%0], %1;" \
        :: "r"((uint32_t)(mbar)), "r"((uint32_t)(count)) : "memory")
__device__ __forceinline__ void mbarrier_inval(uint32_t mbar) {
    asm volatile("mbarrier.inval.shared.b64 [%0];" :: "r"(mbar) : "memory");
}
#define MBARRIER_WAIT_PARITY(mbar_smem_addr, phase_parity) do { \
    uint32_t _mbar = (uint32_t)(mbar_smem_addr); \
    uint32_t _parity = (uint32_t)(phase_parity); \
    uint32_t _done; \
    asm volatile("{\n\t.reg .pred p;\n\t" \
        "mbarrier.try_wait.parity.acquire.cta.shared::cta.b64 p, [%1], %2;\n\t" \
        "selp.b32 %0, 1, 0, p;\n\t}" \
        : "=r"(_done) : "r"(_mbar), "r"(_parity) : "memory"); \
    if (!_done) { \
        asm volatile("{\n\t.reg .pred P1;\n\t" \
            "WAIT_LOOP_%=:\n\t" \
            "mbarrier.try_wait.parity.acquire.cta.shared::cta.b64 P1, [%0], %1, 0x989680;\n\t" \
            "@P1 bra.uni WAIT_DONE_%=;\n\t" \
            "bra.uni WAIT_LOOP_%=;\n\t" \
            "WAIT_DONE_%=:\n\t}" \
            :: "r"(_mbar), "r"(_parity) : "memory"); \
    } \
} while(0)

// cp.async
__device__ __forceinline__ void cp16(uint32_t saddr, const void* gptr) {
    asm volatile("cp.async.cg.shared.global [%0], [%1], 16;" :: "r"(saddr), "l"(gptr));
}
#define CP_COMMIT() asm volatile("cp.async.commit_group;" ::: "memory")
#define CP_WAIT1()  asm volatile("cp.async.wait_group 1;"  ::: "memory")
#define CP_WAIT0()  asm volatile("cp.async.wait_group 0;"  ::: "memory")

// ---------------------------------------------------------------------------
// GEMM configuration: CTA tile 128(M) x 256(N), K-chunk 32, 3-stage pipeline
// ---------------------------------------------------------------------------
#define TILE_M   128
#define TILE_N   256
#define NTH      128
#define NSTAGE   3

// idesc: c=F32(1<<4), a=TF32(2<<7), b=TF32(2<<10), N/4<<16, M/16<<24
static constexpr uint32_t IDESC_TF32 =
    (1u << 4) | (2u << 7) | (2u << 10) | ((TILE_N / 4u) << 16) | ((TILE_M / 16u) << 24);

// SMEM layout (offsets from 1024-aligned sbase):
//   [0]  tmem ptr   [8] mbarrier
//   [1024 + p*49152]          A tile stage p: 128 rows x 128B = 16384
//   [1024 + p*49152 + 16384]  B tile stage p: 256 rows x 128B = 32768
#define STAGE_BYTES 49152
#define SMEM_DYN    (1024 + 1024 + NSTAGE * STAGE_BYTES)

// Scratch (allocation-free rule: device globals)
__device__ float g_v  [B_ * S_ * H_];   // 32 MB
__device__ float g_t  [B_ * S_ * H_];   // 32 MB
__device__ float g_ivn[B_ * S_];        // reciprocal norms
__device__ float g_itn[B_ * S_];

#if HAS_TCGEN05
// ---------------------------------------------------------------------------
// Load one K-chunk (A: 128x32 tf32, B: 256x32 tf32) into a stage, SW128.
// ---------------------------------------------------------------------------
__device__ __forceinline__ void load_chunk(uint32_t sbase, int stage,
                                           const float* __restrict__ A, long arow0,
                                           const float* __restrict__ Bm, long brow0,
                                           int K, int chunk)
{
    const int t  = threadIdx.x;
    const int k0 = chunk << 5;
    const uint32_t aB = sbase + 1024 + stage * STAGE_BYTES;
    const uint32_t bB = aB + 16384;
    #pragma unroll
    for (int it = 0; it < 8; it++) {                 // A: 1024 x 16B
        int idx = t + (it << 7);
        int row = idx >> 3, kq = idx & 7;
        uint32_t off = (uint32_t)(row * 128 + kq * 16);
        cp16(aB + SMEM_SWIZZLE_128B(off), A + (arow0 + row) * (long)K + k0 + (kq << 2));
    }
    #pragma unroll
    for (int it = 0; it < 16; it++) {                // B: 2048 x 16B
        int idx = t + (it << 7);
        int row = idx >> 3, kq = idx & 7;
        uint32_t off = (uint32_t)(row * 128 + kq * 16);
        cp16(bB + SMEM_SWIZZLE_128B(off), Bm + (brow0 + row) * (long)K + k0 + (kq << 2));
    }
}

// ---------------------------------------------------------------------------
// Mainloop: D[128,256] = A[tile] * B[tile]^T over K (K % 32 == 0, K/32 >= 3).
// 3-stage ring: at iter i, MMA i overlaps with the load of chunk i+2 (which
// reuses the stage vacated by the already-completed MMA i-1).
// ---------------------------------------------------------------------------
__device__ __forceinline__ uint32_t gemm_mainloop(uint32_t sbase,
                                                  const float* __restrict__ A, long arow0,
                                                  const float* __restrict__ Bm, long brow0,
                                                  int K)
{
    const int t = threadIdx.x;
    if (t < 32) {
        TCGEN05_ALLOC(sbase + 0, 256);
        TCGEN05_RELINQUISH_ALLOC_PERMIT();
    }
    if (t == 0) MBARRIER_INIT(sbase + 8, 1);

    const int nch = K >> 5;
    load_chunk(sbase, 0, A, arow0, Bm, brow0, K, 0);
    CP_COMMIT();
    load_chunk(sbase, 1, A, arow0, Bm, brow0, K, 1);
    CP_COMMIT();
    __syncthreads();

    uint32_t tmem;
    asm volatile("ld.shared.b32 %0, [%1];" : "=r"(tmem) : "r"(sbase));

    for (int i = 0; i < nch; i++) {
        const int p = i % NSTAGE;
        // Drain enough cp.async groups that chunk i is resident. The most
        // recent commit is chunk min(i+1, nch-1): on the last iteration the
        // newest group IS chunk i, so we must drain to zero (R4 bug: WAIT1
        // here left the final chunk in flight while the MMA read it).
        if (i == nch - 1) { CP_WAIT0(); } else { CP_WAIT1(); }
        __syncthreads();
        if (t < 32) {
            if (elect_one_pred()) {
                FENCE_PROXY_ASYNC_SHARED_CTA();
                const uint32_t aoff = 1024 + p * STAGE_BYTES;
                const uint64_t ad = MAKE_SMEM_DESC(sbase + aoff);
                const uint64_t bd = MAKE_SMEM_DESC(sbase + aoff + 16384);
                #pragma unroll
                for (int s = 0; s < 4; s++)
                    TCGEN05_MMA_TF32(tmem, ad + 2 * s, bd + 2 * s, IDESC_TF32, (i | s) != 0);
                TCGEN05_COMMIT(sbase + 8);
            }
        }
        if (i >= 1) {
            MBARRIER_WAIT_PARITY(sbase + 8, (i - 1) & 1);   // MMA i-1 done
            __syncthreads();
        }
        if (i + 2 < nch) {                // stage (i+2)%3: vacated by MMA i-1
            load_chunk(sbase, (i + 2) % NSTAGE, A, arow0, Bm, brow0, K, i + 2);
            CP_COMMIT();
        }
    }
    MBARRIER_WAIT_PARITY(sbase + 8, (nch - 1) & 1);
    TCGEN05_FENCE_AFTER();
    return tmem;
}

__device__ __forceinline__ void gemm_cleanup(uint32_t sbase, uint32_t tmem)
{
    __syncthreads();
    if (threadIdx.x == 0) mbarrier_inval(sbase + 8);
    __syncthreads();
    if (threadIdx.x < 32) TCGEN05_DEALLOC(tmem, 256);
}
#endif  // HAS_TCGEN05

// ---------------------------------------------------------------------------
// Projection: C[m, n] = sum_k A[m,k] W[n,k] + bias[n]
// grid (N/256, M/128), 128 threads.
// ---------------------------------------------------------------------------
__global__ void __launch_bounds__(NTH, 1)
proj_tc(const float* __restrict__ A, const float* __restrict__ W,
        const float* __restrict__ bias, float* __restrict__ C, int K)
{
#if HAS_TCGEN05
    extern __shared__ char smem[];
    const uint32_t sbase = (smem_to_u32(smem) + 1023u) & ~1023u;
    const long m0 = (long)blockIdx.y * TILE_M;
    const int  n0 = blockIdx.x * TILE_N;

    const uint32_t tmem = gemm_mainloop(sbase, A, m0, W, n0, K);

    const int lane = threadIdx.x & 31;
    const int wid  = threadIdx.x >> 5;
    const long row = m0 + wid * 32 + lane;
    float* __restrict__ crow = C + row * H_;

    #pragma unroll
    for (int cb = 0; cb < TILE_N; cb += 32) {
        uint32_t r[32];
        TCGEN05_LD_32X32B_X32(r, tmem + cb);
        TCGEN05_WAIT_LD();
        #pragma unroll
        for (int j = 0; j < 32; j += 4) {
            const int col = n0 + cb + j;
            float4 bv = *(const float4*)(bias + col);
            float4 o;
            o.x = __uint_as_float(r[j + 0]) + bv.x;
            o.y = __uint_as_float(r[j + 1]) + bv.y;
            o.z = __uint_as_float(r[j + 2]) + bv.z;
            o.w = __uint_as_float(r[j + 3]) + bv.w;
            *(float4*)(crow + col) = o;
        }
    }
    TCGEN05_FENCE_BEFORE();
    gemm_cleanup(sbase, tmem);
#else
    // SIMT fallback (same launch geometry; only runs if non-a cubin is picked)
    const long m0 = (long)blockIdx.y * TILE_M;
    const int  n0 = blockIdx.x * TILE_N;
    for (int idx = threadIdx.x; idx < TILE_M * TILE_N; idx += NTH) {
        const int r = idx / TILE_N, c = idx % TILE_N;
        const float4* ap = (const float4*)(A + (m0 + r) * (long)K);
        const float4* wp = (const float4*)(W + (long)(n0 + c) * K);
        float s = 0.f;
        for (int k = 0; k < K / 4; k++) {
            float4 a = ap[k], w = wp[k];
            s += a.x * w.x + a.y * w.y + a.z * w.z + a.w * w.w;
        }
        C[(m0 + r) * (long)H_ + n0 + c] = s + bias[n0 + c];
    }
#endif
}

// ---------------------------------------------------------------------------
// Batched similarity with fused cosine epilogue (reciprocal-norm multiply):
// C[b,i,j] = dot(v[b,i],t[b,j]) * ivn[b,i] * itn[b,j]
// grid (S/256, S/128, B), 128 threads.
// ---------------------------------------------------------------------------
__global__ void __launch_bounds__(NTH, 1)
sim_tc(const float* __restrict__ V, const float* __restrict__ T,
       const float* __restrict__ IVN, const float* __restrict__ ITN,
       float* __restrict__ C)
{
    const int bz = blockIdx.z;
    const float* A  = V + (long)bz * S_ * H_;
    const float* Bm = T + (long)bz * S_ * H_;
    float*       Cb = C + (long)bz * S_ * S_;
    const long m0 = (long)blockIdx.y * TILE_M;
    const int  n0 = blockIdx.x * TILE_N;
#if HAS_TCGEN05
    extern __shared__ char smem[];
    const uint32_t sbase = (smem_to_u32(smem) + 1023u) & ~1023u;

    const uint32_t tmem = gemm_mainloop(sbase, A, m0, Bm, n0, H_);

    const int lane = threadIdx.x & 31;
    const int wid  = threadIdx.x >> 5;
    const long m   = m0 + wid * 32 + lane;
    const float ivn = IVN[bz * S_ + m];
    const float* itn = ITN + bz * S_;
    float* __restrict__ crow = Cb + m * S_;

    #pragma unroll
    for (int cb = 0; cb < TILE_N; cb += 32) {
        uint32_t r[32];
        TCGEN05_LD_32X32B_X32(r, tmem + cb);
        TCGEN05_WAIT_LD();
        #pragma unroll
        for (int j = 0; j < 32; j += 4) {
            const int col = n0 + cb + j;
            float4 tv = *(const float4*)(itn + col);
            float4 o;
            o.x = __uint_as_float(r[j + 0]) * ivn * tv.x;
            o.y = __uint_as_float(r[j + 1]) * ivn * tv.y;
            o.z = __uint_as_float(r[j + 2]) * ivn * tv.z;
            o.w = __uint_as_float(r[j + 3]) * ivn * tv.w;
            *(float4*)(crow + col) = o;
        }
    }
    TCGEN05_FENCE_BEFORE();
    gemm_cleanup(sbase, tmem);
#else
    for (int idx = threadIdx.x; idx < TILE_M * TILE_N; idx += NTH) {
        const int r = idx / TILE_N, c = idx % TILE_N;
        const float4* ap = (const float4*)(A + (m0 + r) * (long)H_);
        const float4* bp = (const float4*)(Bm + (long)(n0 + c) * H_);
        float s = 0.f;
        for (int k = 0; k < H_ / 4; k++) {
            float4 a = ap[k], b = bp[k];
            s += a.x * b.x + a.y * b.y + a.z * b.z + a.w * b.w;
        }
        Cb[(m0 + r) * (long)S_ + n0 + c] =
            s * IVN[bz * S_ + m0 + r] * ITN[bz * S_ + n0 + c];
    }
#endif
}

// ---------------------------------------------------------------------------
// Row reciprocal L2 norms over H=512: one warp per row.
// ---------------------------------------------------------------------------
__global__ void rownorm_kernel(const float* __restrict__ X, float* __restrict__ out)
{
    const int row  = blockIdx.x * (blockDim.x >> 5) + (threadIdx.x >> 5);
    const int lane = threadIdx.x & 31;
    const float4* p = (const float4*)(X + (long)row * H_);
    float s = 0.f;
    #pragma unroll
    for (int i = lane; i < H_ / 4; i += 32) {
        float4 v = p[i];
        s += v.x * v.x + v.y * v.y + v.z * v.z + v.w * v.w;
    }
    #pragma unroll
    for (int o = 16; o; o >>= 1) s += __shfl_xor_sync(0xFFFFFFFFu, s, o);
    if (lane == 0) out[row] = 1.0f / sqrtf(s);
}

// ---------------------------------------------------------------------------
extern "C" void kernel_launch(void* const* d_in, const int* in_sizes, int n_in,
                              void* d_out, int out_size)
{
    const float* visual = (const float*)d_in[0];  // [16,1024,1024]
    const float* text   = (const float*)d_in[1];  // [16,1024,768]
    const float* Wv     = (const float*)d_in[2];  // [512,1024]
    const float* bv     = (const float*)d_in[3];  // [512]
    const float* Wt     = (const float*)d_in[4];  // [512,768]
    const float* bt     = (const float*)d_in[5];  // [512]
    float* out = (float*)d_out;                   // [16,1024,1024]

    float *v, *tt, *ivn, *itn;
    cudaGetSymbolAddress((void**)&v,   g_v);
    cudaGetSymbolAddress((void**)&tt,  g_t);
    cudaGetSymbolAddress((void**)&ivn, g_ivn);
    cudaGetSymbolAddress((void**)&itn, g_itn);

    cudaFuncSetAttribute(proj_tc, cudaFuncAttributeMaxDynamicSharedMemorySize, SMEM_DYN);
    cudaFuncSetAttribute(sim_tc,  cudaFuncAttributeMaxDynamicSharedMemorySize, SMEM_DYN);

    const int M = B_ * S_;  // 16384

    // Projections: [M, 512] = A[M, K] @ W[512, K]^T + bias
    proj_tc<<<dim3(H_ / TILE_N, M / TILE_M), NTH, SMEM_DYN>>>(visual, Wv, bv, v,  VD_);
    proj_tc<<<dim3(H_ / TILE_N, M / TILE_M), NTH, SMEM_DYN>>>(text,   Wt, bt, tt, TD_);

    // Reciprocal row norms
    rownorm_kernel<<<M / 8, 256>>>(v,  ivn);
    rownorm_kernel<<<M / 8, 256>>>(tt, itn);

    // Batched similarity with fused cosine epilogue
    sim_tc<<<dim3(S_ / TILE_N, S_ / TILE_M, B_), NTH, SMEM_DYN>>>(v, tt, ivn, itn, out);
}